// round 16
// baseline (speedup 1.0000x reference)
#include <cuda_runtime.h>
#include <cuda_fp16.h>
#include <cstdint>

#define HDIM  1024
#define BATCH 2048
#define SEQL  96
#define VOCAB 96
#define NBH   (BATCH * HDIM)
#define HH    ((size_t)HDIM * HDIM)
#define WFCS  ((size_t)128 * HDIM)

typedef unsigned int u32;

// fp16 main operands (A0 / B0) + packed int8 correction operands (P / Q)
__device__ float g_h0f[NBH];
__device__ float g_h1f[NBH];
__device__ float g_tmp[NBH];
__device__ float g_logits[(size_t)SEQL * BATCH * VOCAB];
__device__ float g_bias0[HDIM];
__device__ float g_bias1[HDIM];
__device__ __half g_h0s[2][NBH];
__device__ signed char g_h0q[2][2ULL * NBH];
__device__ __half g_h1s[(SEQL + 1) * (size_t)NBH];
__device__ signed char g_h1q[(SEQL + 1) * 2ULL * NBH];
__device__ __half g_w0hh[HH];
__device__ signed char g_w0q[2 * HH];
__device__ __half g_w1ih[HH];
__device__ signed char g_w1iq[2 * HH];
__device__ __half g_w1hh[HH];
__device__ signed char g_w1hq[2 * HH];
__device__ __half g_wfc[WFCS];
__device__ signed char g_wfcq[2 * WFCS];

__device__ __forceinline__ u32 smem_u32(const void* p) {
    u32 a; asm("{ .reg .u64 t; cvta.to.shared.u64 t, %1; cvt.u32.u64 %0, t; }" : "=r"(a) : "l"(p));
    return a;
}
__device__ __forceinline__ void cpa16(u32 s, const void* g) {
    asm volatile("cp.async.cg.shared.global [%0], [%1], 16;" :: "r"(s), "l"(g) : "memory");
}
__device__ __forceinline__ void ldsm4(u32* r, u32 a) {
    asm volatile("ldmatrix.sync.aligned.m8n8.x4.shared.b16 {%0,%1,%2,%3}, [%4];"
                 : "=r"(r[0]), "=r"(r[1]), "=r"(r[2]), "=r"(r[3]) : "r"(a));
}
__device__ __forceinline__ void mma_f32(float* c, const u32* a, u32 b0, u32 b1) {
    asm volatile("mma.sync.aligned.m16n8k16.row.col.f32.f16.f16.f32 "
                 "{%0,%1,%2,%3}, {%4,%5,%6,%7}, {%8,%9}, {%0,%1,%2,%3};"
                 : "+f"(c[0]), "+f"(c[1]), "+f"(c[2]), "+f"(c[3])
                 : "r"(a[0]), "r"(a[1]), "r"(a[2]), "r"(a[3]), "r"(b0), "r"(b1));
}
__device__ __forceinline__ void mma_s8(int* c, const u32* a, u32 b0, u32 b1) {
    asm volatile("mma.sync.aligned.m16n8k32.row.col.s32.s8.s8.s32 "
                 "{%0,%1,%2,%3}, {%4,%5,%6,%7}, {%8,%9}, {%0,%1,%2,%3};"
                 : "+r"(c[0]), "+r"(c[1]), "+r"(c[2]), "+r"(c[3])
                 : "r"(a[0]), "r"(a[1]), "r"(a[2]), "r"(a[3]), "r"(b0), "r"(b1));
}

// ---- quantization constants ----
// A0 scale 127; A1 scale 127*2^12; B0 scale 127*2^5; B1 scale 127*2^17.
// product scale both halves = 127^2 * 2^17 = 2114453504
#define SC_A1 520192.0f      // 127*4096
#define SC_B0 4064.0f        // 127*32
#define SC_B1 16646144.0f    // 127*131072
#define DQ    (1.0f / 2114453504.0f)

// ------------------------------ prep ------------------------------------------
__device__ __forceinline__ void prep_w(float w, __half* fp, signed char* q, size_t j) {
    size_t n = j >> 10, k = j & 1023;
    __half h = __float2half_rn(w);
    fp[j] = h;
    float hf = __half2float(h);
    size_t qoff = n * 2048 + ((k >> 6) << 7) + (k & 63);
    q[qoff]      = (signed char)__float2int_rn((w - hf) * SC_B1);  // b1
    q[qoff + 64] = (signed char)__float2int_rn(hf * SC_B0);        // b0
}

__global__ void prep_kernel(const float* __restrict__ w0hh, const float* __restrict__ w1ih,
                            const float* __restrict__ w1hh, const float* __restrict__ fcw,
                            const float* __restrict__ b0a, const float* __restrict__ b0b,
                            const float* __restrict__ b1a, const float* __restrict__ b1b) {
    size_t i = (size_t)blockIdx.x * blockDim.x + threadIdx.x;
    size_t st = (size_t)gridDim.x * blockDim.x;
    if (i < HDIM) { g_bias0[i] = b0a[i] + b0b[i]; g_bias1[i] = b1a[i] + b1b[i]; }
    for (size_t j = i; j < HH; j += st) {
        prep_w(w0hh[j], g_w0hh, g_w0q, j);
        prep_w(w1ih[j], g_w1ih, g_w1iq, j);
        prep_w(w1hh[j], g_w1hh, g_w1hq, j);
    }
    for (size_t j = i; j < WFCS; j += st) {
        size_t n = j >> 10, k = j & 1023;
        float v = (n < VOCAB) ? fcw[n * HDIM + k] : 0.0f;
        prep_w(v, g_wfc, g_wfcq, j);
    }
    __half z = __float2half_rn(0.0f);
    for (size_t j = i; j < NBH; j += st) { g_h0s[0][j] = z; g_h1s[j] = z; }
    for (size_t j = i; j < 2ULL * NBH; j += st) { g_h0q[0][j] = 0; g_h1q[j] = 0; }
}

// ---------------- GEMM core: C(64x128); main fp16 + int8 packed corrections ----
#define RSB    144
#define A0_OFF 0
#define P_OFF  (64 * RSB)               // 9216
#define B0_OFF (2 * 64 * RSB)           // 18432
#define Q_OFF  (B0_OFF + 128 * RSB)     // 36864
#define STG_B  (Q_OFF + 128 * RSB)      // 55296
#define SMEM_BYTES (2 * STG_B)          // 110592

__device__ __forceinline__ void gemm_core(
    const __half* __restrict__ Afp, const signed char* __restrict__ Aq,
    const __half* __restrict__ Wfp, const signed char* __restrict__ Wq,
    int m0, int n0, u32 sb, int tid, int lane, int wm, int wn,
    float (&c)[2][4][4])
{
    auto load_chunk = [&](int ch) {
        const int kc = ch * 64;
        const u32 stg = sb + (u32)(ch & 1) * STG_B;
        #pragma unroll
        for (int it = 0; it < 12; ++it) {
            int g = tid + it * 256;
            u32 dst; const void* src;
            if (g < 512) {
                int r = g >> 3, s = g & 7;
                src = Afp + (size_t)(m0 + r) * HDIM + kc + s * 8;
                dst = stg + A0_OFF + (u32)(r * RSB + s * 16);
            } else if (g < 1024) {
                int i2 = g - 512, r = i2 >> 3, s = i2 & 7;
                src = Aq + (size_t)(m0 + r) * 2048 + ch * 128 + s * 16;
                dst = stg + P_OFF + (u32)(r * RSB + s * 16);
            } else if (g < 2048) {
                int i2 = g - 1024, r = i2 >> 3, s = i2 & 7;
                src = Wfp + (size_t)(n0 + r) * HDIM + kc + s * 8;
                dst = stg + B0_OFF + (u32)(r * RSB + s * 16);
            } else {
                int i2 = g - 2048, r = i2 >> 3, s = i2 & 7;
                src = Wq + (size_t)(n0 + r) * 2048 + ch * 128 + s * 16;
                dst = stg + Q_OFF + (u32)(r * RSB + s * 16);
            }
            cpa16(dst, src);
        }
        asm volatile("cp.async.commit_group;" ::: "memory");
    };

    load_chunk(0);
    load_chunk(1);

    const u32 arow = (u32)((wm + (lane & 15)) * RSB) + (u32)((lane >> 4) * 16);
    const u32 brow = (u32)((wn + (lane & 15)) * RSB) + (u32)((lane >> 4) * 16);

    for (int ch = 0; ch < 16; ++ch) {
        if (ch < 14) asm volatile("cp.async.wait_group 1;" ::: "memory");
        else         asm volatile("cp.async.wait_group 0;" ::: "memory");
        __syncthreads();

        const u32 stg = sb + (u32)(ch & 1) * STG_B;

        // ---- fp16 main term: A0 @ B0 ----
        #pragma unroll
        for (int ks = 0; ks < 4; ++ks) {
            const u32 kb = (u32)(ks * 32);
            u32 a[2][4], b[2][4];
            #pragma unroll
            for (int mm = 0; mm < 2; ++mm)
                ldsm4(a[mm], stg + A0_OFF + arow + (u32)(mm * 16 * RSB) + kb);
            #pragma unroll
            for (int ng = 0; ng < 2; ++ng)
                ldsm4(b[ng], stg + B0_OFF + brow + (u32)(ng * 16 * RSB) + kb);
            #pragma unroll
            for (int mm = 0; mm < 2; ++mm)
                #pragma unroll
                for (int ng = 0; ng < 2; ++ng) {
                    mma_f32(c[mm][ng * 2],     a[mm], b[ng][0], b[ng][2]);
                    mma_f32(c[mm][ng * 2 + 1], a[mm], b[ng][1], b[ng][3]);
                }
        }

        // ---- int8 packed corrections: P @ Q = A0*B1 + A1*B0 (scaled) ----
        int cI[2][4][4];
        #pragma unroll
        for (int mm = 0; mm < 2; ++mm)
            #pragma unroll
            for (int nn = 0; nn < 4; ++nn)
                #pragma unroll
                for (int q = 0; q < 4; ++q) cI[mm][nn][q] = 0;
        #pragma unroll
        for (int ki = 0; ki < 4; ++ki) {
            const u32 kb = (u32)(ki * 32);
            u32 aI[2][4], bI[2][4];
            #pragma unroll
            for (int mm = 0; mm < 2; ++mm)
                ldsm4(aI[mm], stg + P_OFF + arow + (u32)(mm * 16 * RSB) + kb);
            #pragma unroll
            for (int ng = 0; ng < 2; ++ng)
                ldsm4(bI[ng], stg + Q_OFF + brow + (u32)(ng * 16 * RSB) + kb);
            #pragma unroll
            for (int mm = 0; mm < 2; ++mm)
                #pragma unroll
                for (int ng = 0; ng < 2; ++ng) {
                    mma_s8(cI[mm][ng * 2],     aI[mm], bI[ng][0], bI[ng][2]);
                    mma_s8(cI[mm][ng * 2 + 1], aI[mm], bI[ng][1], bI[ng][3]);
                }
        }
        #pragma unroll
        for (int mm = 0; mm < 2; ++mm)
            #pragma unroll
            for (int nn = 0; nn < 4; ++nn)
                #pragma unroll
                for (int q = 0; q < 4; ++q)
                    c[mm][nn][q] += (float)cI[mm][nn][q] * DQ;

        __syncthreads();
        if (ch + 2 < 16) load_chunk(ch + 2);
    }
}

#define ACC_INIT(c) { _Pragma("unroll") for (int i = 0; i < 2; ++i) \
    _Pragma("unroll") for (int j = 0; j < 4; ++j) \
    _Pragma("unroll") for (int q = 0; q < 4; ++q) (c)[i][j][q] = 0.0f; }

// store h pair: fp16 A0 + int8 (a0q, a1q) packed operands
__device__ __forceinline__ void store_h_pair(
    __half* fpbuf, signed char* qbuf, int m, int n, float ha, float hb)
{
    size_t off = (size_t)m * HDIM + n;
    __half a0 = __float2half_rn(ha), b0 = __float2half_rn(hb);
    *(__half2*)(fpbuf + off) = __halves2half2(a0, b0);
    float a0f = __half2float(a0), b0f = __half2float(b0);
    int q0a = __float2int_rn(a0f * 127.0f);
    int q0b = __float2int_rn(b0f * 127.0f);
    int q1a = __float2int_rn((ha - a0f) * SC_A1);
    int q1b = __float2int_rn((hb - b0f) * SC_A1);
    size_t qoff = (size_t)m * 2048 + (size_t)((n >> 6) << 7) + (n & 63);
    *(unsigned short*)(qbuf + qoff)      = (unsigned short)((q0a & 0xff) | ((q0b & 0xff) << 8));
    *(unsigned short*)(qbuf + qoff + 64) = (unsigned short)((q1a & 0xff) | ((q1b & 0xff) << 8));
}

// ---- step1: y<32 -> U1 (h0 update); y>=32 -> U2 (g_tmp + bias1) ---------------
__global__ void __launch_bounds__(256, 2)
step1_kernel(const __half* __restrict__ h0c, const signed char* __restrict__ h0cq,
             const __half* __restrict__ h1c, const signed char* __restrict__ h1cq,
             __half* __restrict__ h0n, signed char* __restrict__ h0nq,
             float* __restrict__ h0f,
             const float* __restrict__ x, const float* __restrict__ wcol, int t)
{
    extern __shared__ __align__(16) char smem[];
    const u32 sb = smem_u32(smem);
    const int tid = threadIdx.x, wid = tid >> 5, lane = tid & 31;
    const bool is_tmp = blockIdx.y >= 32;
    const int m0 = (is_tmp ? ((int)blockIdx.y - 32) : (int)blockIdx.y) << 6;
    const int n0 = blockIdx.x << 7;
    const int wm = (wid & 1) * 32, wn = (wid >> 1) * 32;

    float c[2][4][4]; ACC_INIT(c);
    if (is_tmp) gemm_core(h1c, h1cq, g_w1hh, g_w1hq, m0, n0, sb, tid, lane, wm, wn, c);
    else        gemm_core(h0c, h0cq, g_w0hh, g_w0q,  m0, n0, sb, tid, lane, wm, wn, c);

    #pragma unroll
    for (int mm = 0; mm < 2; ++mm)
        #pragma unroll
        for (int h8 = 0; h8 < 2; ++h8) {
            int m = m0 + wm + mm * 16 + (lane >> 2) + h8 * 8;
            float xv = is_tmp ? 0.0f : x[(size_t)m * SEQL + t];
            #pragma unroll
            for (int nn = 0; nn < 4; ++nn) {
                int n = n0 + wn + nn * 8 + (lane & 3) * 2;
                size_t off = (size_t)m * HDIM + n;
                float v0 = c[mm][nn][h8 * 2], v1 = c[mm][nn][h8 * 2 + 1];
                if (is_tmp) {
                    *(float2*)(g_tmp + off) = make_float2(v0 + g_bias1[n],
                                                          v1 + g_bias1[n + 1]);
                } else {
                    v0 += g_bias0[n]     + xv * wcol[n];
                    v1 += g_bias0[n + 1] + xv * wcol[n + 1];
                    float ha = tanhf(v0), hb = tanhf(v1);
                    if (h0f) *(float2*)(h0f + off) = make_float2(ha, hb);
                    store_h_pair(h0n, h0nq, m, n, ha, hb);
                }
            }
        }
}

// ---- step2: y<32 -> U3; y>=32 -> fc GEMM for fc_t -----------------------------
__global__ void __launch_bounds__(256, 2)
step2_kernel(const __half* __restrict__ h0n, const signed char* __restrict__ h0nq,
             __half* __restrict__ h1n, signed char* __restrict__ h1nq,
             float* __restrict__ h1f,
             const __half* __restrict__ hfc, const signed char* __restrict__ hfcq,
             const float* __restrict__ fcb, int fc_t)
{
    extern __shared__ __align__(16) char smem[];
    const u32 sb = smem_u32(smem);
    const int tid = threadIdx.x, wid = tid >> 5, lane = tid & 31;
    const int wm = (wid & 1) * 32, wn = (wid >> 1) * 32;

    if (blockIdx.y < 32) {
        const int m0 = blockIdx.y << 6, n0 = blockIdx.x << 7;
        float c[2][4][4]; ACC_INIT(c);
        gemm_core(h0n, h0nq, g_w1ih, g_w1iq, m0, n0, sb, tid, lane, wm, wn, c);
        #pragma unroll
        for (int mm = 0; mm < 2; ++mm)
            #pragma unroll
            for (int h8 = 0; h8 < 2; ++h8) {
                int m = m0 + wm + mm * 16 + (lane >> 2) + h8 * 8;
                #pragma unroll
                for (int nn = 0; nn < 4; ++nn) {
                    int n = n0 + wn + nn * 8 + (lane & 3) * 2;
                    size_t off = (size_t)m * HDIM + n;
                    float2 tv = *(const float2*)(g_tmp + off);
                    float ha = tanhf(c[mm][nn][h8 * 2]     + tv.x);
                    float hb = tanhf(c[mm][nn][h8 * 2 + 1] + tv.y);
                    if (h1f) *(float2*)(h1f + off) = make_float2(ha, hb);
                    store_h_pair(h1n, h1nq, m, n, ha, hb);
                }
            }
    } else {
        if (fc_t < 0) return;
        const int mb = ((int)blockIdx.y - 32) * 8 + (int)blockIdx.x;   // 0..31
        const int m0 = mb << 6;
        float c[2][4][4]; ACC_INIT(c);
        gemm_core(hfc, hfcq, g_wfc, g_wfcq, m0, 0, sb, tid, lane, wm, wn, c);
        if (wn >= VOCAB) return;
        #pragma unroll
        for (int mm = 0; mm < 2; ++mm)
            #pragma unroll
            for (int h8 = 0; h8 < 2; ++h8) {
                int m = m0 + wm + mm * 16 + (lane >> 2) + h8 * 8;
                size_t row = (size_t)fc_t * BATCH + m;
                #pragma unroll
                for (int nn = 0; nn < 4; ++nn) {
                    int n = wn + nn * 8 + (lane & 3) * 2;
                    if (n < VOCAB) {
                        float v0 = c[mm][nn][h8 * 2]     + fcb[n];
                        float v1 = c[mm][nn][h8 * 2 + 1] + fcb[n + 1];
                        *(float2*)(g_logits + row * VOCAB + n) = make_float2(v0, v1);
                    }
                }
            }
    }
}

// ---- fc for the last timestep ---------------------------------------------------
__global__ void __launch_bounds__(256, 2)
fc_last_kernel(const __half* __restrict__ hfc, const signed char* __restrict__ hfcq,
               const float* __restrict__ fcb, int t)
{
    extern __shared__ __align__(16) char smem[];
    const u32 sb = smem_u32(smem);
    const int tid = threadIdx.x, wid = tid >> 5, lane = tid & 31;
    const int wm = (wid & 1) * 32, wn = (wid >> 1) * 32;
    const int m0 = (int)blockIdx.x << 6;

    float c[2][4][4]; ACC_INIT(c);
    gemm_core(hfc, hfcq, g_wfc, g_wfcq, m0, 0, sb, tid, lane, wm, wn, c);

    if (wn >= VOCAB) return;
    #pragma unroll
    for (int mm = 0; mm < 2; ++mm)
        #pragma unroll
        for (int h8 = 0; h8 < 2; ++h8) {
            int m = m0 + wm + mm * 16 + (lane >> 2) + h8 * 8;
            size_t row = (size_t)t * BATCH + m;
            #pragma unroll
            for (int nn = 0; nn < 4; ++nn) {
                int n = wn + nn * 8 + (lane & 3) * 2;
                if (n < VOCAB) {
                    float v0 = c[mm][nn][h8 * 2]     + fcb[n];
                    float v1 = c[mm][nn][h8 * 2 + 1] + fcb[n + 1];
                    *(float2*)(g_logits + row * VOCAB + n) = make_float2(v0, v1);
                }
            }
        }
}

// ---- sequential argmax patch ------------------------------------------------------
__device__ __forceinline__ int wargmax3(float v0, float v1, float v2, int lane) {
    float mv = v0; int mi = lane;
    if (v1 > mv) { mv = v1; mi = lane + 32; }
    if (v2 > mv) { mv = v2; mi = lane + 64; }
    #pragma unroll
    for (int o = 16; o; o >>= 1) {
        float ov = __shfl_xor_sync(0xffffffffu, mv, o);
        int oi = __shfl_xor_sync(0xffffffffu, mi, o);
        if (ov > mv || (ov == mv && oi < mi)) { mv = ov; mi = oi; }
    }
    return mi;
}

__global__ void adjust_kernel(float* __restrict__ out) {
    int gw = (blockIdx.x * blockDim.x + threadIdx.x) >> 5;
    int lane = threadIdx.x & 31;
    if (gw >= BATCH) return;
    int prevarg = 0;
    for (int t = 0; t < SEQL; ++t) {
        const float* row = g_logits + ((size_t)t * BATCH + gw) * VOCAB;
        float v0 = row[lane], v1 = row[lane + 32], v2 = row[lane + 64];
        int curarg = wargmax3(v0, v1, v2, lane);
        if (t > 0) {
            if (prevarg == 0 && curarg != 1 && lane == 1) v0 += 0.5f;
            if (t == SEQL - 1 && curarg == 0 && lane == 0) v0 -= 0.5f;
        }
        float* o = out + ((size_t)gw * SEQL + t) * VOCAB;
        o[lane] = v0; o[lane + 32] = v1; o[lane + 64] = v2;
        prevarg = wargmax3(v0, v1, v2, lane);
    }
}

__global__ void copy_hidden_kernel(float* __restrict__ out2) {
    int i = blockIdx.x * blockDim.x + threadIdx.x;
    if (i < NBH) { out2[i] = g_h0f[i]; out2[NBH + i] = g_h1f[i]; }
}

extern "C" void kernel_launch(void* const* d_in, const int* in_sizes, int n_in,
                              void* d_out, int out_size)
{
    const float* x      = (const float*)d_in[0];
    const float* l0_Wih = (const float*)d_in[1];
    const float* l0_Whh = (const float*)d_in[2];
    const float* l0_bih = (const float*)d_in[3];
    const float* l0_bhh = (const float*)d_in[4];
    const float* l1_Wih = (const float*)d_in[5];
    const float* l1_Whh = (const float*)d_in[6];
    const float* l1_bih = (const float*)d_in[7];
    const float* l1_bhh = (const float*)d_in[8];
    const float* fc_W   = (const float*)d_in[9];
    const float* fc_b   = (const float*)d_in[10];

    void* p;
    cudaGetSymbolAddress(&p, g_h0f); float* h0f = (float*)p;
    cudaGetSymbolAddress(&p, g_h1f); float* h1f = (float*)p;
    cudaGetSymbolAddress(&p, g_h0s); __half* h0s = (__half*)p;
    cudaGetSymbolAddress(&p, g_h0q); signed char* h0q = (signed char*)p;
    cudaGetSymbolAddress(&p, g_h1s); __half* h1s = (__half*)p;
    cudaGetSymbolAddress(&p, g_h1q); signed char* h1q = (signed char*)p;

    cudaFuncSetAttribute(step1_kernel,   cudaFuncAttributeMaxDynamicSharedMemorySize, SMEM_BYTES);
    cudaFuncSetAttribute(step2_kernel,   cudaFuncAttributeMaxDynamicSharedMemorySize, SMEM_BYTES);
    cudaFuncSetAttribute(fc_last_kernel, cudaFuncAttributeMaxDynamicSharedMemorySize, SMEM_BYTES);

    prep_kernel<<<1024, 256>>>(l0_Whh, l1_Wih, l1_Whh, fc_W,
                               l0_bih, l0_bhh, l1_bih, l1_bhh);

    for (int t = 0; t < SEQL; ++t) {
        __half* h0c = h0s + (size_t)(t & 1) * NBH;
        __half* h0n = h0s + (size_t)((t & 1) ^ 1) * NBH;
        signed char* h0cq = h0q + (size_t)(t & 1) * 2 * NBH;
        signed char* h0nq = h0q + (size_t)((t & 1) ^ 1) * 2 * NBH;
        __half* h1c = h1s + (size_t)t * NBH;
        __half* h1n = h1s + (size_t)(t + 1) * NBH;
        signed char* h1cq = h1q + (size_t)t * 2 * NBH;
        signed char* h1nq = h1q + (size_t)(t + 1) * 2 * NBH;

        step1_kernel<<<dim3(8, 64), 256, SMEM_BYTES>>>(
            h0c, h0cq, h1c, h1cq, h0n, h0nq,
            (t == SEQL - 1) ? h0f : nullptr, x, l0_Wih, t);
        step2_kernel<<<dim3(8, 36), 256, SMEM_BYTES>>>(
            h0n, h0nq, h1n, h1nq, (t == SEQL - 1) ? h1f : nullptr,
            h1c, h1cq, fc_b, t - 1);   // fc for t-1 reads h1 slot t = h1c
    }

    fc_last_kernel<<<32, 256, SMEM_BYTES>>>(
        h1s + (size_t)SEQL * NBH, h1q + (size_t)SEQL * 2 * NBH, fc_b, SEQL - 1);

    float* out = (float*)d_out;
    adjust_kernel<<<BATCH / 8, 256>>>(out);
    copy_hidden_kernel<<<(NBH + 255) / 256, 256>>>(out + (size_t)BATCH * SEQL * VOCAB);
}

// round 17
// speedup vs baseline: 1.9849x; 1.9849x over previous
#include <cuda_runtime.h>
#include <cuda_fp16.h>
#include <cstdint>

#define HDIM  1024
#define BATCH 2048
#define SEQL  96
#define VOCAB 96
#define NBH   (BATCH * HDIM)
#define HH    ((size_t)HDIM * HDIM)
#define WFCS  ((size_t)128 * HDIM)
#define SP    (2ULL * NBH)

typedef unsigned int u32;

__device__ float g_h0f[NBH];
__device__ float g_h1f[NBH];
__device__ float g_tmp[NBH];
__device__ float g_logits[(size_t)SEQL * BATCH * VOCAB];
__device__ float g_bias0[HDIM];
__device__ float g_bias1[HDIM];
__device__ __half g_h0s[2][SP];
__device__ __half g_h1s[(SEQL + 1) * SP];
__device__ __half g_w0hh[2 * HH];
__device__ __half g_w1ih[2 * HH];
__device__ __half g_w1hh[2 * HH];
__device__ __half g_wfc[2 * WFCS];

__device__ __forceinline__ u32 smem_u32(const void* p) {
    u32 a; asm("{ .reg .u64 t; cvta.to.shared.u64 t, %1; cvt.u32.u64 %0, t; }" : "=r"(a) : "l"(p));
    return a;
}
__device__ __forceinline__ void cpa16(u32 s, const void* g) {
    asm volatile("cp.async.cg.shared.global [%0], [%1], 16;" :: "r"(s), "l"(g) : "memory");
}
__device__ __forceinline__ void ldsm4(u32& r0, u32& r1, u32& r2, u32& r3, u32 a) {
    asm volatile("ldmatrix.sync.aligned.m8n8.x4.shared.b16 {%0,%1,%2,%3}, [%4];"
                 : "=r"(r0), "=r"(r1), "=r"(r2), "=r"(r3) : "r"(a));
}
__device__ __forceinline__ void mma_f32(float* c, const u32* a, u32 b0, u32 b1) {
    asm volatile("mma.sync.aligned.m16n8k16.row.col.f32.f16.f16.f32 "
                 "{%0,%1,%2,%3}, {%4,%5,%6,%7}, {%8,%9}, {%0,%1,%2,%3};"
                 : "+f"(c[0]), "+f"(c[1]), "+f"(c[2]), "+f"(c[3])
                 : "r"(a[0]), "r"(a[1]), "r"(a[2]), "r"(a[3]), "r"(b0), "r"(b1));
}
__device__ __forceinline__ void mma_f16(u32* c, const u32* a, u32 b0, u32 b1) {
    asm volatile("mma.sync.aligned.m16n8k16.row.col.f16.f16.f16.f16 "
                 "{%0,%1}, {%2,%3,%4,%5}, {%6,%7}, {%0,%1};"
                 : "+r"(c[0]), "+r"(c[1])
                 : "r"(a[0]), "r"(a[1]), "r"(a[2]), "r"(a[3]), "r"(b0), "r"(b1));
}
__device__ __forceinline__ void split2(float v, __half* d, size_t j, size_t st) {
    __half a = __float2half_rn(v);
    d[j] = a;
    d[st + j] = __float2half_rn(v - __half2float(a));
}

// ------------------------------ prep ------------------------------------------
__global__ void prep_kernel(const float* __restrict__ w0hh, const float* __restrict__ w1ih,
                            const float* __restrict__ w1hh, const float* __restrict__ fcw,
                            const float* __restrict__ b0a, const float* __restrict__ b0b,
                            const float* __restrict__ b1a, const float* __restrict__ b1b) {
    size_t i = (size_t)blockIdx.x * blockDim.x + threadIdx.x;
    size_t st = (size_t)gridDim.x * blockDim.x;
    if (i < HDIM) { g_bias0[i] = b0a[i] + b0b[i]; g_bias1[i] = b1a[i] + b1b[i]; }
    for (size_t j = i; j < HH; j += st) {
        split2(w0hh[j], g_w0hh, j, HH);
        split2(w1ih[j], g_w1ih, j, HH);
        split2(w1hh[j], g_w1hh, j, HH);
    }
    for (size_t j = i; j < WFCS; j += st) {
        size_t n = j >> 10, k = j & 1023;
        float v = (n < VOCAB) ? fcw[n * HDIM + k] : 0.0f;
        split2(v, g_wfc, j, WFCS);
    }
    __half z = __float2half_rn(0.0f);
    for (size_t j = i; j < SP; j += st) { g_h0s[0][j] = z; g_h1s[j] = z; }
}

// ---------------- shared GEMM core: C(64x128) = split-3 product ----------------
#define RSB   144
#define A_TB  (64 * RSB)
#define W_TB  (128 * RSB)
#define STG_B (2 * A_TB + 2 * W_TB)   // 55296
#define SMEM_BYTES (2 * STG_B)        // 110592

__device__ __forceinline__ void gemm_core(
    const __half* __restrict__ A, const __half* __restrict__ W, size_t wstride,
    int m0, int n0, u32 sb, int tid, int lane, int wm, int wn,
    float (&c)[2][4][4])
{
    u32 cH[2][4][2];
    #pragma unroll
    for (int i = 0; i < 2; ++i)
        #pragma unroll
        for (int j = 0; j < 4; ++j) { cH[i][j][0] = 0u; cH[i][j][1] = 0u; }

    auto load_chunk = [&](int ch) {
        const int kc = ch * 64;
        const u32 stg = sb + (u32)(ch & 1) * STG_B;
        #pragma unroll
        for (int it = 0; it < 12; ++it) {
            int g = tid + it * 256;
            const __half* src; u32 dst;
            if (g < 1024) {
                int tile = g >> 9, idx = g & 511, r = idx >> 3, seg = idx & 7;
                src = A + (size_t)tile * NBH + (size_t)(m0 + r) * HDIM + kc + seg * 8;
                dst = stg + (u32)tile * A_TB + (u32)(r * RSB + seg * 16);
            } else {
                int g2 = g - 1024;
                int tile = g2 >> 10, idx = g2 & 1023, r = idx >> 3, seg = idx & 7;
                src = W + (size_t)tile * wstride + (size_t)(n0 + r) * HDIM + kc + seg * 8;
                dst = stg + 2 * A_TB + (u32)tile * W_TB + (u32)(r * RSB + seg * 16);
            }
            cpa16(dst, src);
        }
        asm volatile("cp.async.commit_group;" ::: "memory");
    };

    load_chunk(0);
    load_chunk(1);

    const u32 aoff = (u32)((wm + (lane & 15)) * RSB) + (u32)((lane >> 4) * 16);
    const u32 boff = (u32)((wn + (lane & 15)) * RSB) + (u32)((lane >> 4) * 16);

    for (int ch = 0; ch < 16; ++ch) {
        if (ch < 14) asm volatile("cp.async.wait_group 1;" ::: "memory");
        else         asm volatile("cp.async.wait_group 0;" ::: "memory");
        __syncthreads();

        const u32 stg = sb + (u32)(ch & 1) * STG_B;
        const u32 Ab = stg + aoff;
        const u32 Wb = stg + 2 * A_TB + boff;

        #pragma unroll
        for (int ks = 0; ks < 4; ++ks) {
            const u32 kb = (u32)(ks * 32);
            u32 a[2][2][4], b[2][2][4];
            #pragma unroll
            for (int s = 0; s < 2; ++s)
                #pragma unroll
                for (int mm = 0; mm < 2; ++mm)
                    ldsm4(a[s][mm][0], a[s][mm][1], a[s][mm][2], a[s][mm][3],
                          Ab + (u32)s * A_TB + (u32)(mm * 16 * RSB) + kb);
            #pragma unroll
            for (int s = 0; s < 2; ++s)
                #pragma unroll
                for (int ng = 0; ng < 2; ++ng)
                    ldsm4(b[s][ng][0], b[s][ng][1], b[s][ng][2], b[s][ng][3],
                          Wb + (u32)s * W_TB + (u32)(ng * 16 * RSB) + kb);

            // term-major issue order: no back-to-back dependent accumulators.
            // term 1: main A0*B0 (f32 acc) — 8 independent HMMA
            #pragma unroll
            for (int mm = 0; mm < 2; ++mm)
                #pragma unroll
                for (int ng = 0; ng < 2; ++ng) {
                    mma_f32(c[mm][ng * 2],     a[0][mm], b[0][ng][0], b[0][ng][2]);
                    mma_f32(c[mm][ng * 2 + 1], a[0][mm], b[0][ng][1], b[0][ng][3]);
                }
            // term 2: A0*B1 (f16 acc) — 8 independent HMMA
            #pragma unroll
            for (int mm = 0; mm < 2; ++mm)
                #pragma unroll
                for (int ng = 0; ng < 2; ++ng) {
                    mma_f16(cH[mm][ng * 2],     a[0][mm], b[1][ng][0], b[1][ng][2]);
                    mma_f16(cH[mm][ng * 2 + 1], a[0][mm], b[1][ng][1], b[1][ng][3]);
                }
            // term 3: A1*B0 (f16 acc) — depends on term 2, 8-instr gap
            #pragma unroll
            for (int mm = 0; mm < 2; ++mm)
                #pragma unroll
                for (int ng = 0; ng < 2; ++ng) {
                    mma_f16(cH[mm][ng * 2],     a[1][mm], b[0][ng][0], b[0][ng][2]);
                    mma_f16(cH[mm][ng * 2 + 1], a[1][mm], b[0][ng][1], b[0][ng][3]);
                }
        }
        __syncthreads();
        if (ch + 2 < 16) load_chunk(ch + 2);
    }

    #pragma unroll
    for (int mm = 0; mm < 2; ++mm)
        #pragma unroll
        for (int nn = 0; nn < 4; ++nn) {
            __half2 p0 = *reinterpret_cast<__half2*>(&cH[mm][nn][0]);
            __half2 p1 = *reinterpret_cast<__half2*>(&cH[mm][nn][1]);
            c[mm][nn][0] += __low2float(p0);  c[mm][nn][1] += __high2float(p0);
            c[mm][nn][2] += __low2float(p1);  c[mm][nn][3] += __high2float(p1);
        }
}

#define ACC_INIT(c) { _Pragma("unroll") for (int i = 0; i < 2; ++i) \
    _Pragma("unroll") for (int j = 0; j < 4; ++j) \
    _Pragma("unroll") for (int q = 0; q < 4; ++q) (c)[i][j][q] = 0.0f; }

// ---- step1: blocks y<32 -> U1 (h0 update); y>=32 -> U2 (g_tmp + bias1) ------
__global__ void __launch_bounds__(256, 2)
step1_kernel(const __half* __restrict__ h0cur, const __half* __restrict__ h1cur,
             __half* __restrict__ h0nxt, float* __restrict__ h0f,
             const float* __restrict__ x, const float* __restrict__ wcol, int t)
{
    extern __shared__ __align__(16) char smem[];
    const u32 sb = smem_u32(smem);
    const int tid = threadIdx.x, wid = tid >> 5, lane = tid & 31;
    const bool is_tmp = blockIdx.y >= 32;
    const int m0 = (is_tmp ? ((int)blockIdx.y - 32) : (int)blockIdx.y) << 6;
    const int n0 = blockIdx.x << 7;
    const int wm = (wid & 1) * 32, wn = (wid >> 1) * 32;

    float c[2][4][4]; ACC_INIT(c);
    gemm_core(is_tmp ? h1cur : h0cur, is_tmp ? g_w1hh : g_w0hh, HH,
              m0, n0, sb, tid, lane, wm, wn, c);

    #pragma unroll
    for (int mm = 0; mm < 2; ++mm)
        #pragma unroll
        for (int h8 = 0; h8 < 2; ++h8) {
            int m = m0 + wm + mm * 16 + (lane >> 2) + h8 * 8;
            float xv = is_tmp ? 0.0f : x[(size_t)m * SEQL + t];
            #pragma unroll
            for (int nn = 0; nn < 4; ++nn) {
                int n = n0 + wn + nn * 8 + (lane & 3) * 2;
                size_t off = (size_t)m * HDIM + n;
                float v0 = c[mm][nn][h8 * 2], v1 = c[mm][nn][h8 * 2 + 1];
                if (is_tmp) {
                    *(float2*)(g_tmp + off) = make_float2(v0 + g_bias1[n],
                                                          v1 + g_bias1[n + 1]);
                } else {
                    v0 += g_bias0[n]     + xv * wcol[n];
                    v1 += g_bias0[n + 1] + xv * wcol[n + 1];
                    float ha = tanhf(v0), hb = tanhf(v1);
                    if (h0f) *(float2*)(h0f + off) = make_float2(ha, hb);
                    __half a0 = __float2half_rn(ha), b0 = __float2half_rn(hb);
                    *(__half2*)(h0nxt + off) = __halves2half2(a0, b0);
                    *(__half2*)(h0nxt + NBH + off) = __halves2half2(
                        __float2half_rn(ha - __half2float(a0)),
                        __float2half_rn(hb - __half2float(b0)));
                }
            }
        }
}

// ---- step2: y<32 -> U3 = tanh(h0'@W1ih^T + tmp); y>=32 -> fc GEMM for fc_t --
__global__ void __launch_bounds__(256, 2)
step2_kernel(const __half* __restrict__ h0nxt, __half* __restrict__ h1nxt,
             float* __restrict__ h1f, const float* __restrict__ fcb, int fc_t)
{
    extern __shared__ __align__(16) char smem[];
    const u32 sb = smem_u32(smem);
    const int tid = threadIdx.x, wid = tid >> 5, lane = tid & 31;
    const int wm = (wid & 1) * 32, wn = (wid >> 1) * 32;

    if (blockIdx.y < 32) {
        const int m0 = blockIdx.y << 6, n0 = blockIdx.x << 7;
        float c[2][4][4]; ACC_INIT(c);
        gemm_core(h0nxt, g_w1ih, HH, m0, n0, sb, tid, lane, wm, wn, c);

        #pragma unroll
        for (int mm = 0; mm < 2; ++mm)
            #pragma unroll
            for (int h8 = 0; h8 < 2; ++h8) {
                int m = m0 + wm + mm * 16 + (lane >> 2) + h8 * 8;
                #pragma unroll
                for (int nn = 0; nn < 4; ++nn) {
                    int n = n0 + wn + nn * 8 + (lane & 3) * 2;
                    size_t off = (size_t)m * HDIM + n;
                    float2 tv = *(const float2*)(g_tmp + off);
                    float ha = tanhf(c[mm][nn][h8 * 2]     + tv.x);
                    float hb = tanhf(c[mm][nn][h8 * 2 + 1] + tv.y);
                    if (h1f) *(float2*)(h1f + off) = make_float2(ha, hb);
                    __half a0 = __float2half_rn(ha), b0 = __float2half_rn(hb);
                    *(__half2*)(h1nxt + off) = __halves2half2(a0, b0);
                    *(__half2*)(h1nxt + NBH + off) = __halves2half2(
                        __float2half_rn(ha - __half2float(a0)),
                        __float2half_rn(hb - __half2float(b0)));
                }
            }
    } else {
        if (fc_t < 0) return;
        const int mb = ((int)blockIdx.y - 32) * 8 + (int)blockIdx.x;   // 0..31
        const int m0 = mb << 6;
        const __half* A = g_h1s + (size_t)(fc_t + 1) * SP;

        float c[2][4][4]; ACC_INIT(c);
        gemm_core(A, g_wfc, WFCS, m0, 0, sb, tid, lane, wm, wn, c);

        if (wn >= VOCAB) return;
        #pragma unroll
        for (int mm = 0; mm < 2; ++mm)
            #pragma unroll
            for (int h8 = 0; h8 < 2; ++h8) {
                int m = m0 + wm + mm * 16 + (lane >> 2) + h8 * 8;
                size_t row = (size_t)fc_t * BATCH + m;
                #pragma unroll
                for (int nn = 0; nn < 4; ++nn) {
                    int n = wn + nn * 8 + (lane & 3) * 2;
                    if (n < VOCAB) {
                        float v0 = c[mm][nn][h8 * 2]     + fcb[n];
                        float v1 = c[mm][nn][h8 * 2 + 1] + fcb[n + 1];
                        *(float2*)(g_logits + row * VOCAB + n) = make_float2(v0, v1);
                    }
                }
            }
    }
}

// ---- fc for the last timestep ------------------------------------------------
__global__ void __launch_bounds__(256, 2)
fc_last_kernel(const float* __restrict__ fcb, int t)
{
    extern __shared__ __align__(16) char smem[];
    const u32 sb = smem_u32(smem);
    const int tid = threadIdx.x, wid = tid >> 5, lane = tid & 31;
    const int wm = (wid & 1) * 32, wn = (wid >> 1) * 32;
    const int m0 = (int)blockIdx.x << 6;
    const __half* A = g_h1s + (size_t)(t + 1) * SP;

    float c[2][4][4]; ACC_INIT(c);
    gemm_core(A, g_wfc, WFCS, m0, 0, sb, tid, lane, wm, wn, c);

    if (wn >= VOCAB) return;
    #pragma unroll
    for (int mm = 0; mm < 2; ++mm)
        #pragma unroll
        for (int h8 = 0; h8 < 2; ++h8) {
            int m = m0 + wm + mm * 16 + (lane >> 2) + h8 * 8;
            size_t row = (size_t)t * BATCH + m;
            #pragma unroll
            for (int nn = 0; nn < 4; ++nn) {
                int n = wn + nn * 8 + (lane & 3) * 2;
                if (n < VOCAB) {
                    float v0 = c[mm][nn][h8 * 2]     + fcb[n];
                    float v1 = c[mm][nn][h8 * 2 + 1] + fcb[n + 1];
                    *(float2*)(g_logits + row * VOCAB + n) = make_float2(v0, v1);
                }
            }
        }
}

// ---- sequential argmax patch ---------------------------------------------------
__device__ __forceinline__ int wargmax3(float v0, float v1, float v2, int lane) {
    float mv = v0; int mi = lane;
    if (v1 > mv) { mv = v1; mi = lane + 32; }
    if (v2 > mv) { mv = v2; mi = lane + 64; }
    #pragma unroll
    for (int o = 16; o; o >>= 1) {
        float ov = __shfl_xor_sync(0xffffffffu, mv, o);
        int oi = __shfl_xor_sync(0xffffffffu, mi, o);
        if (ov > mv || (ov == mv && oi < mi)) { mv = ov; mi = oi; }
    }
    return mi;
}

__global__ void adjust_kernel(float* __restrict__ out) {
    int gw = (blockIdx.x * blockDim.x + threadIdx.x) >> 5;
    int lane = threadIdx.x & 31;
    if (gw >= BATCH) return;
    int prevarg = 0;
    for (int t = 0; t < SEQL; ++t) {
        const float* row = g_logits + ((size_t)t * BATCH + gw) * VOCAB;
        float v0 = row[lane], v1 = row[lane + 32], v2 = row[lane + 64];
        int curarg = wargmax3(v0, v1, v2, lane);
        if (t > 0) {
            if (prevarg == 0 && curarg != 1 && lane == 1) v0 += 0.5f;
            if (t == SEQL - 1 && curarg == 0 && lane == 0) v0 -= 0.5f;
        }
        float* o = out + ((size_t)gw * SEQL + t) * VOCAB;
        o[lane] = v0; o[lane + 32] = v1; o[lane + 64] = v2;
        prevarg = wargmax3(v0, v1, v2, lane);
    }
}

__global__ void copy_hidden_kernel(float* __restrict__ out2) {
    int i = blockIdx.x * blockDim.x + threadIdx.x;
    if (i < NBH) { out2[i] = g_h0f[i]; out2[NBH + i] = g_h1f[i]; }
}

extern "C" void kernel_launch(void* const* d_in, const int* in_sizes, int n_in,
                              void* d_out, int out_size)
{
    const float* x      = (const float*)d_in[0];
    const float* l0_Wih = (const float*)d_in[1];
    const float* l0_Whh = (const float*)d_in[2];
    const float* l0_bih = (const float*)d_in[3];
    const float* l0_bhh = (const float*)d_in[4];
    const float* l1_Wih = (const float*)d_in[5];
    const float* l1_Whh = (const float*)d_in[6];
    const float* l1_bih = (const float*)d_in[7];
    const float* l1_bhh = (const float*)d_in[8];
    const float* fc_W   = (const float*)d_in[9];
    const float* fc_b   = (const float*)d_in[10];

    void* p;
    cudaGetSymbolAddress(&p, g_h0f); float* h0f = (float*)p;
    cudaGetSymbolAddress(&p, g_h1f); float* h1f = (float*)p;
    cudaGetSymbolAddress(&p, g_h0s); __half* h0s = (__half*)p;
    cudaGetSymbolAddress(&p, g_h1s); __half* h1s = (__half*)p;

    cudaFuncSetAttribute(step1_kernel,   cudaFuncAttributeMaxDynamicSharedMemorySize, SMEM_BYTES);
    cudaFuncSetAttribute(step2_kernel,   cudaFuncAttributeMaxDynamicSharedMemorySize, SMEM_BYTES);
    cudaFuncSetAttribute(fc_last_kernel, cudaFuncAttributeMaxDynamicSharedMemorySize, SMEM_BYTES);

    prep_kernel<<<1024, 256>>>(l0_Whh, l1_Wih, l1_Whh, fc_W,
                               l0_bih, l0_bhh, l1_bih, l1_bhh);

    for (int t = 0; t < SEQL; ++t) {
        __half* h0_cur = h0s + (size_t)(t & 1) * SP;
        __half* h0_nxt = h0s + (size_t)((t & 1) ^ 1) * SP;
        __half* h1_cur = h1s + (size_t)t * SP;
        __half* h1_nxt = h1s + (size_t)(t + 1) * SP;
        step1_kernel<<<dim3(8, 64), 256, SMEM_BYTES>>>(
            h0_cur, h1_cur, h0_nxt, (t == SEQL - 1) ? h0f : nullptr, x, l0_Wih, t);
        step2_kernel<<<dim3(8, 36), 256, SMEM_BYTES>>>(
            h0_nxt, h1_nxt, (t == SEQL - 1) ? h1f : nullptr, fc_b, t - 1);
    }

    fc_last_kernel<<<32, 256, SMEM_BYTES>>>(fc_b, SEQL - 1);

    float* out = (float*)d_out;
    adjust_kernel<<<BATCH / 8, 256>>>(out);
    copy_hidden_kernel<<<(NBH + 255) / 256, 256>>>(out + (size_t)BATCH * SEQL * VOCAB);
}